// round 13
// baseline (speedup 1.0000x reference)
#include <cuda_runtime.h>
#include <cuda_bf16.h>
#include <cstdint>

// Problem constants (fixed by the reference)
#define BATCH 524288
#define NFEAT 8

#define TPB 128
#define ROWS 512                         // rows per block
#define NBLOCKS (BATCH / ROWS)           // 1024
#define CHUNK 256                        // rows per TMA chunk
#define NCHUNK (ROWS / CHUNK)            // 2
#define CHUNK_BYTES (CHUNK * 32)         // 8 KB
#define TILE_BYTES (ROWS * 32)           // 16 KB
#define EPC (CHUNK / TPB)                // 2 elements per thread per chunk

#define FULLMASK 0xFFFFFFFFu

__device__ __forceinline__ uint32_t smem_u32(const void* p) {
    uint32_t a;
    asm("{ .reg .u64 t; cvta.to.shared.u64 t, %1; cvt.u32.u64 %0, t; }"
        : "=r"(a) : "l"(p));
    return a;
}

__device__ __forceinline__ void mbar_wait(uint32_t mbar_a) {
    uint32_t done;
    asm volatile(
        "{\n\t"
        ".reg .pred p;\n\t"
        "mbarrier.try_wait.parity.acquire.cta.shared::cta.b64 p, [%1], %2;\n\t"
        "selp.b32 %0, 1, 0, p;\n\t"
        "}"
        : "=r"(done) : "r"(mbar_a), "r"(0u) : "memory");
    if (!done) {
        asm volatile(
            "{\n\t"
            ".reg .pred P1;\n\t"
            "WAIT_LOOP_%=:\n\t"
            "mbarrier.try_wait.parity.acquire.cta.shared::cta.b64 P1, [%0], %1, 0x989680;\n\t"
            "@P1 bra.uni WAIT_DONE_%=;\n\t"
            "bra.uni WAIT_LOOP_%=;\n\t"
            "WAIT_DONE_%=:\n\t"
            "}"
            :: "r"(mbar_a), "r"(0u) : "memory");
    }
}

// Single fused kernel, chunked-TMA pipeline:
//  - thread 0 launches 2 x 8KB TMA bulk copies (separate mbarriers)
//  - warp 0 computes the 27-coeff contraction tensor T via shuffles while
//    the TMA chunks are in flight
//  - per chunk: mbarrier wait -> compute 2 elements/thread from smem:
//    out = sum_{a,b,c} T[a,b,c] * v0_a*v1_b*v2_c, v_i = (1, cos x_i, sin x_i)
__global__ void __launch_bounds__(TPB) vqc_kernel(
    const char* __restrict__ xbytes, float* __restrict__ out,
    const float* __restrict__ w) {

    __shared__ __align__(128) char tile[TILE_BYTES];
    __shared__ __align__(16) float sT[28];
    __shared__ __align__(8) unsigned long long mbar[NCHUNK];

    const int tid = threadIdx.x;
    const int lane = tid & 31;
    const uint32_t tile_a = smem_u32(tile);
    const uint32_t mbar_a0 = smem_u32(&mbar[0]);

    // ---- mbarrier init ----
    if (tid == 0) {
#pragma unroll
        for (int c = 0; c < NCHUNK; c++) {
            asm volatile("mbarrier.init.shared.b64 [%0], %1;"
                         :: "r"(mbar_a0 + 8 * c), "r"(1) : "memory");
        }
    }
    __syncthreads();

    // ---- Issue all chunk copies up front (independent mbarriers) ----
    if (tid == 0) {
        const char* src = xbytes + (size_t)blockIdx.x * TILE_BYTES;
#pragma unroll
        for (int c = 0; c < NCHUNK; c++) {
            const uint32_t mb = mbar_a0 + 8 * c;
            asm volatile("mbarrier.arrive.expect_tx.shared.b64 _, [%0], %1;"
                         :: "r"(mb), "r"((uint32_t)CHUNK_BYTES) : "memory");
            asm volatile(
                "cp.async.bulk.shared::cluster.global.mbarrier::complete_tx::bytes "
                "[%0], [%1], %2, [%3];"
                :: "r"(tile_a + c * CHUNK_BYTES), "l"(src + c * CHUNK_BYTES),
                   "r"((uint32_t)CHUNK_BYTES), "r"(mb)
                : "memory");
        }
    }

    // ================= Warp 0: compute T via shuffles (overlaps TMA) =========
    if (tid < 32) {
        // -- 18 half-angle sincos, one per lane (clamped index) --
        float cw, sw;
        {
            const int wi = lane < 18 ? lane : 17;
            __sincosf(0.5f * __ldg(&w[wi]), &sw, &cw);
        }

        // -- Each lane simulates column `lane` of V (lanes >=8 carry junk) --
        float re[8], im[8];
#pragma unroll
        for (int k = 0; k < 8; k++) {
            re[k] = (k == lane) ? 1.0f : 0.0f;
            im[k] = 0.0f;
        }

#pragma unroll
        for (int l = 0; l < 3; l++) {
#pragma unroll
            for (int q = 0; q < 3; q++) {
                const int g = l * 3 + q;
                const float cy = __shfl_sync(FULLMASK, cw, 2 * g);
                const float sy = __shfl_sync(FULLMASK, sw, 2 * g);
                const float cz = __shfl_sync(FULLMASK, cw, 2 * g + 1);
                const float sz = __shfl_sync(FULLMASK, sw, 2 * g + 1);
                const int bit = 4 >> q;  // qubit q occupies bit (2-q)
#pragma unroll
                for (int j = 0; j < 8; j++) {
                    if (j & bit) continue;
                    const int j1 = j | bit;
                    const float r0 = re[j],  i0 = im[j];
                    const float r1 = re[j1], i1 = im[j1];
                    // RY(th)
                    const float nr0 = cy * r0 - sy * r1;
                    const float ni0 = cy * i0 - sy * i1;
                    const float nr1 = sy * r0 + cy * r1;
                    const float ni1 = sy * i0 + cy * i1;
                    // RZ(ph): amp(bit=0) *= cz - i sz ; amp(bit=1) *= cz + i sz
                    re[j]  = cz * nr0 + sz * ni0;
                    im[j]  = cz * ni0 - sz * nr0;
                    re[j1] = cz * nr1 - sz * ni1;
                    im[j1] = cz * ni1 + sz * nr1;
                }
            }
            // CNOT(0,1): control bit4, target bit2
#pragma unroll
            for (int j = 0; j < 8; j++) {
                if ((j & 4) && !(j & 2)) {
                    const int j1 = j | 2;
                    float tmp;
                    tmp = re[j]; re[j] = re[j1]; re[j1] = tmp;
                    tmp = im[j]; im[j] = im[j1]; im[j1] = tmp;
                }
            }
            // CNOT(1,2): control bit2, target bit1
#pragma unroll
            for (int j = 0; j < 8; j++) {
                if ((j & 2) && !(j & 1)) {
                    const int j1 = j | 1;
                    float tmp;
                    tmp = re[j]; re[j] = re[j1]; re[j1] = tmp;
                    tmp = im[j]; im[j] = im[j1]; im[j1] = tmp;
                }
            }
        }

        // -- M = Re(V^H Z0 V): lane holds m0 = M[j0][k0], m1 = M[j0+4][k0] --
        const int j0 = lane >> 3, k0 = lane & 7;
        float m0 = 0.0f, m1 = 0.0f;
#pragma unroll
        for (int r = 0; r < 8; r++) {
            const float arj  = __shfl_sync(FULLMASK, re[r], j0);
            const float aij  = __shfl_sync(FULLMASK, im[r], j0);
            const float arj4 = __shfl_sync(FULLMASK, re[r], j0 + 4);
            const float aij4 = __shfl_sync(FULLMASK, im[r], j0 + 4);
            const float ark  = __shfl_sync(FULLMASK, re[r], k0);
            const float aik  = __shfl_sync(FULLMASK, im[r], k0);
            const float zr = (r < 4) ? 1.0f : -1.0f;
            m0 += zr * (arj  * ark + aij  * aik);
            m1 += zr * (arj4 * ark + aij4 * aik);
        }

        // -- T[a,b,c] (lane < 27): signed 8-term sum of M entries --
        const int a = lane / 9, b = (lane / 3) % 3, c = lane % 3;
        const int fa = (a == 2), fb = (b == 2), fc = (c == 2);
        const int na = (a == 1), nb = (b == 1), nc = (c == 1);
        float acc = 0.0f;
#pragma unroll
        for (int i0 = 0; i0 < 2; i0++)
#pragma unroll
            for (int i1 = 0; i1 < 2; i1++)
#pragma unroll
                for (int i2 = 0; i2 < 2; i2++) {
                    const int j = (i0 << 2) | (i1 << 1) | i2;
                    const int k = ((i0 ^ fa) << 2) | ((i1 ^ fb) << 1) | (i2 ^ fc);
                    const int idx = j * 8 + k;
                    const float v0 = __shfl_sync(FULLMASK, m0, idx & 31);
                    const float v1 = __shfl_sync(FULLMASK, m1, idx & 31);
                    const float mv = i0 ? v1 : v0;  // j>=4 <=> i0
                    const int neg = (na & i0) ^ (nb & i1) ^ (nc & i2);
                    acc += neg ? -mv : mv;
                }

        if (lane < 27) sT[lane] = 0.125f * acc;
        if (lane == 27) sT[27] = 0.0f;
    }
    __syncthreads();   // publishes sT; TMA completion tracked by mbarriers

    // ---- T via 7 vector LDS.128 (broadcast) ----
    float T[28];
    {
        const float4* sT4 = (const float4*)sT;
#pragma unroll
        for (int i = 0; i < 7; i++) {
            const float4 t = sT4[i];
            T[4 * i + 0] = t.x; T[4 * i + 1] = t.y;
            T[4 * i + 2] = t.z; T[4 * i + 3] = t.w;
        }
    }

    // ================= Chunked compute: start as each 8KB lands =============
    const int gbase = blockIdx.x * ROWS;
#pragma unroll
    for (int c = 0; c < NCHUNK; c++) {
        mbar_wait(mbar_a0 + 8 * c);

#pragma unroll
        for (int e = 0; e < EPC; e++) {
            const int row = c * CHUNK + e * TPB + tid;
            const float4 xv = *(const float4*)(tile + 32 * row);  // first 16B

            float c0, s0, c1, s1, c2, s2;
            __sincosf(xv.x, &s0, &c0);
            __sincosf(xv.y, &s1, &c1);
            __sincosf(xv.z, &s2, &c2);

            float u[3];
#pragma unroll
            for (int a2 = 0; a2 < 3; a2++) {
                float wb[3];
#pragma unroll
                for (int b2 = 0; b2 < 3; b2++) {
                    const float* Tb = &T[a2 * 9 + b2 * 3];
                    wb[b2] = Tb[0] + Tb[1] * c2 + Tb[2] * s2;
                }
                u[a2] = wb[0] + wb[1] * c1 + wb[2] * s1;
            }
            out[gbase + row] = u[0] + u[1] * c0 + u[2] * s0;
        }
    }
}

extern "C" void kernel_launch(void* const* d_in, const int* in_sizes, int n_in,
                              void* d_out, int out_size) {
    const char* x = (const char*)d_in[0];          // [BATCH, 8] f32 rows (32B)
    const float* w = (const float*)d_in[1];        // [3, 3, 2]
    float* out = (float*)d_out;                    // [BATCH, 1]

    vqc_kernel<<<NBLOCKS, TPB>>>(x, out, w);
}

// round 15
// speedup vs baseline: 1.0623x; 1.0623x over previous
#include <cuda_runtime.h>
#include <cuda_bf16.h>
#include <cstdint>

// Problem constants (fixed by the reference)
#define BATCH 524288
#define NFEAT 8

#define TPB 256
#define ROWS 1024                        // rows per block
#define NBLOCKS (BATCH / ROWS)           // 512
#define CHUNK 256                        // rows per TMA chunk
#define NCHUNK (ROWS / CHUNK)            // 4
#define CHUNK_BYTES (CHUNK * 32)         // 8 KB
#define TILE_BYTES (ROWS * 32)           // 32 KB

#define FULLMASK 0xFFFFFFFFu

__device__ __forceinline__ uint32_t smem_u32(const void* p) {
    uint32_t a;
    asm("{ .reg .u64 t; cvta.to.shared.u64 t, %1; cvt.u32.u64 %0, t; }"
        : "=r"(a) : "l"(p));
    return a;
}

__device__ __forceinline__ void mbar_wait(uint32_t mbar_a) {
    uint32_t done;
    asm volatile(
        "{\n\t"
        ".reg .pred p;\n\t"
        "mbarrier.try_wait.parity.acquire.cta.shared::cta.b64 p, [%1], %2;\n\t"
        "selp.b32 %0, 1, 0, p;\n\t"
        "}"
        : "=r"(done) : "r"(mbar_a), "r"(0u) : "memory");
    if (!done) {
        asm volatile(
            "{\n\t"
            ".reg .pred P1;\n\t"
            "WAIT_LOOP_%=:\n\t"
            "mbarrier.try_wait.parity.acquire.cta.shared::cta.b64 P1, [%0], %1, 0x989680;\n\t"
            "@P1 bra.uni WAIT_DONE_%=;\n\t"
            "bra.uni WAIT_LOOP_%=;\n\t"
            "WAIT_DONE_%=:\n\t"
            "}"
            :: "r"(mbar_a), "r"(0u) : "memory");
    }
}

// Single fused kernel, chunked-TMA pipeline (consolidated best structure):
//  - thread 0 launches 4 x 8KB TMA bulk copies (separate mbarriers)
//  - warp 0 computes the 27-coeff contraction tensor T via register math +
//    shuffles while the TMA chunks are in flight
//  - per chunk: mbarrier wait -> compute 1 element/thread from smem:
//    out = sum_{a,b,c} T[a,b,c] * v0_a*v1_b*v2_c, v_i = (1, cos x_i, sin x_i)
__global__ void __launch_bounds__(TPB) vqc_kernel(
    const char* __restrict__ xbytes, float* __restrict__ out,
    const float* __restrict__ w) {

    __shared__ __align__(128) char tile[TILE_BYTES];
    __shared__ __align__(16) float sT[28];
    __shared__ __align__(8) unsigned long long mbar[NCHUNK];

    const int tid = threadIdx.x;
    const int lane = tid & 31;
    const uint32_t tile_a = smem_u32(tile);
    const uint32_t mbar_a0 = smem_u32(&mbar[0]);

    // ---- mbarrier init ----
    if (tid == 0) {
#pragma unroll
        for (int c = 0; c < NCHUNK; c++) {
            asm volatile("mbarrier.init.shared.b64 [%0], %1;"
                         :: "r"(mbar_a0 + 8 * c), "r"(1) : "memory");
        }
    }
    __syncthreads();

    // ---- Issue all chunk copies up front (independent mbarriers) ----
    if (tid == 0) {
        const char* src = xbytes + (size_t)blockIdx.x * TILE_BYTES;
#pragma unroll
        for (int c = 0; c < NCHUNK; c++) {
            const uint32_t mb = mbar_a0 + 8 * c;
            asm volatile("mbarrier.arrive.expect_tx.shared.b64 _, [%0], %1;"
                         :: "r"(mb), "r"((uint32_t)CHUNK_BYTES) : "memory");
            asm volatile(
                "cp.async.bulk.shared::cluster.global.mbarrier::complete_tx::bytes "
                "[%0], [%1], %2, [%3];"
                :: "r"(tile_a + c * CHUNK_BYTES), "l"(src + c * CHUNK_BYTES),
                   "r"((uint32_t)CHUNK_BYTES), "r"(mb)
                : "memory");
        }
    }

    // ================= Warp 0: compute T via shuffles (overlaps TMA) =========
    if (tid < 32) {
        // -- 18 half-angle sincos, one per lane (clamped index) --
        float cw, sw;
        {
            const int wi = lane < 18 ? lane : 17;
            __sincosf(0.5f * __ldg(&w[wi]), &sw, &cw);
        }

        // -- Each lane simulates column `lane` of V (lanes >=8 carry junk) --
        float re[8], im[8];
#pragma unroll
        for (int k = 0; k < 8; k++) {
            re[k] = (k == lane) ? 1.0f : 0.0f;
            im[k] = 0.0f;
        }

#pragma unroll
        for (int l = 0; l < 3; l++) {
#pragma unroll
            for (int q = 0; q < 3; q++) {
                const int g = l * 3 + q;
                const float cy = __shfl_sync(FULLMASK, cw, 2 * g);
                const float sy = __shfl_sync(FULLMASK, sw, 2 * g);
                const float cz = __shfl_sync(FULLMASK, cw, 2 * g + 1);
                const float sz = __shfl_sync(FULLMASK, sw, 2 * g + 1);
                const int bit = 4 >> q;  // qubit q occupies bit (2-q)
#pragma unroll
                for (int j = 0; j < 8; j++) {
                    if (j & bit) continue;
                    const int j1 = j | bit;
                    const float r0 = re[j],  i0 = im[j];
                    const float r1 = re[j1], i1 = im[j1];
                    // RY(th)
                    const float nr0 = cy * r0 - sy * r1;
                    const float ni0 = cy * i0 - sy * i1;
                    const float nr1 = sy * r0 + cy * r1;
                    const float ni1 = sy * i0 + cy * i1;
                    // RZ(ph): amp(bit=0) *= cz - i sz ; amp(bit=1) *= cz + i sz
                    re[j]  = cz * nr0 + sz * ni0;
                    im[j]  = cz * ni0 - sz * nr0;
                    re[j1] = cz * nr1 - sz * ni1;
                    im[j1] = cz * ni1 + sz * nr1;
                }
            }
            // CNOT(0,1): control bit4, target bit2
#pragma unroll
            for (int j = 0; j < 8; j++) {
                if ((j & 4) && !(j & 2)) {
                    const int j1 = j | 2;
                    float tmp;
                    tmp = re[j]; re[j] = re[j1]; re[j1] = tmp;
                    tmp = im[j]; im[j] = im[j1]; im[j1] = tmp;
                }
            }
            // CNOT(1,2): control bit2, target bit1
#pragma unroll
            for (int j = 0; j < 8; j++) {
                if ((j & 2) && !(j & 1)) {
                    const int j1 = j | 1;
                    float tmp;
                    tmp = re[j]; re[j] = re[j1]; re[j1] = tmp;
                    tmp = im[j]; im[j] = im[j1]; im[j1] = tmp;
                }
            }
        }

        // -- M = Re(V^H Z0 V): lane holds m0 = M[j0][k0], m1 = M[j0+4][k0] --
        const int j0 = lane >> 3, k0 = lane & 7;
        float m0 = 0.0f, m1 = 0.0f;
#pragma unroll
        for (int r = 0; r < 8; r++) {
            const float arj  = __shfl_sync(FULLMASK, re[r], j0);
            const float aij  = __shfl_sync(FULLMASK, im[r], j0);
            const float arj4 = __shfl_sync(FULLMASK, re[r], j0 + 4);
            const float aij4 = __shfl_sync(FULLMASK, im[r], j0 + 4);
            const float ark  = __shfl_sync(FULLMASK, re[r], k0);
            const float aik  = __shfl_sync(FULLMASK, im[r], k0);
            const float zr = (r < 4) ? 1.0f : -1.0f;
            m0 += zr * (arj  * ark + aij  * aik);
            m1 += zr * (arj4 * ark + aij4 * aik);
        }

        // -- T[a,b,c] (lane < 27): signed 8-term sum of M entries --
        const int a = lane / 9, b = (lane / 3) % 3, c = lane % 3;
        const int fa = (a == 2), fb = (b == 2), fc = (c == 2);
        const int na = (a == 1), nb = (b == 1), nc = (c == 1);
        float acc = 0.0f;
#pragma unroll
        for (int i0 = 0; i0 < 2; i0++)
#pragma unroll
            for (int i1 = 0; i1 < 2; i1++)
#pragma unroll
                for (int i2 = 0; i2 < 2; i2++) {
                    const int j = (i0 << 2) | (i1 << 1) | i2;
                    const int k = ((i0 ^ fa) << 2) | ((i1 ^ fb) << 1) | (i2 ^ fc);
                    const int idx = j * 8 + k;
                    const float v0 = __shfl_sync(FULLMASK, m0, idx & 31);
                    const float v1 = __shfl_sync(FULLMASK, m1, idx & 31);
                    const float mv = i0 ? v1 : v0;  // j>=4 <=> i0
                    const int neg = (na & i0) ^ (nb & i1) ^ (nc & i2);
                    acc += neg ? -mv : mv;
                }

        if (lane < 27) sT[lane] = 0.125f * acc;
        if (lane == 27) sT[27] = 0.0f;
    }
    __syncthreads();   // publishes sT; TMA completion tracked by mbarriers

    // ---- T via 7 vector LDS.128 (broadcast) ----
    float T[28];
    {
        const float4* sT4 = (const float4*)sT;
#pragma unroll
        for (int i = 0; i < 7; i++) {
            const float4 t = sT4[i];
            T[4 * i + 0] = t.x; T[4 * i + 1] = t.y;
            T[4 * i + 2] = t.z; T[4 * i + 3] = t.w;
        }
    }

    // ================= Chunked compute: start as each 8KB lands =============
    const int gbase = blockIdx.x * ROWS;
#pragma unroll
    for (int c = 0; c < NCHUNK; c++) {
        mbar_wait(mbar_a0 + 8 * c);

        const int row = c * CHUNK + tid;
        const float4 xv = *(const float4*)(tile + 32 * row);  // first 16B of row

        float c0, s0, c1, s1, c2, s2;
        __sincosf(xv.x, &s0, &c0);
        __sincosf(xv.y, &s1, &c1);
        __sincosf(xv.z, &s2, &c2);

        float u[3];
#pragma unroll
        for (int a2 = 0; a2 < 3; a2++) {
            float wb[3];
#pragma unroll
            for (int b2 = 0; b2 < 3; b2++) {
                const float* Tb = &T[a2 * 9 + b2 * 3];
                wb[b2] = Tb[0] + Tb[1] * c2 + Tb[2] * s2;
            }
            u[a2] = wb[0] + wb[1] * c1 + wb[2] * s1;
        }
        out[gbase + row] = u[0] + u[1] * c0 + u[2] * s0;
    }
}

extern "C" void kernel_launch(void* const* d_in, const int* in_sizes, int n_in,
                              void* d_out, int out_size) {
    const char* x = (const char*)d_in[0];          // [BATCH, 8] f32 rows (32B)
    const float* w = (const float*)d_in[1];        // [3, 3, 2]
    float* out = (float*)d_out;                    // [BATCH, 1]

    vqc_kernel<<<NBLOCKS, TPB>>>(x, out, w);
}

// round 17
// speedup vs baseline: 1.1818x; 1.1126x over previous
#include <cuda_runtime.h>
#include <cuda_bf16.h>
#include <cstdint>

// Problem constants (fixed by the reference)
#define BATCH 524288
#define NFEAT 8

#define TPB 256
#define ROWS 1024                        // rows per block
#define NBLOCKS (BATCH / ROWS)           // 512
#define EPT (ROWS / TPB)                 // 4 elements per thread
#define TILE_BYTES (ROWS * 32)           // 32 KB (full 32B rows)

#define FULLMASK 0xFFFFFFFFu

// Single fused kernel:
//  - thread 0 launches one 32KB TMA bulk copy (full x-rows) into smem
//  - warp 0 computes the 27-coeff contraction tensor T via register math +
//    shuffles while the TMA is in flight
//  - mbarrier wait + one __syncthreads, then 4 elements/thread from smem:
//    out = sum_{a,b,c} T[a,b,c] * v0_a*v1_b*v2_c, v_i = (1, cos x_i, sin x_i)
__global__ void __launch_bounds__(TPB) vqc_kernel(
    const char* __restrict__ xbytes, float* __restrict__ out,
    const float* __restrict__ w) {

    __shared__ __align__(128) char tile[TILE_BYTES];
    __shared__ __align__(16) float sT[28];
    __shared__ __align__(8) unsigned long long mbar;

    const int tid = threadIdx.x;
    const int lane = tid & 31;
    uint32_t tile_a, mbar_a;
    asm("{ .reg .u64 t; cvta.to.shared.u64 t, %1; cvt.u32.u64 %0, t; }"
        : "=r"(tile_a) : "l"((const void*)tile));
    asm("{ .reg .u64 t; cvta.to.shared.u64 t, %1; cvt.u32.u64 %0, t; }"
        : "=r"(mbar_a) : "l"((const void*)&mbar));

    // ---- mbarrier init ----
    if (tid == 0) {
        asm volatile("mbarrier.init.shared.b64 [%0], %1;"
                     :: "r"(mbar_a), "r"(1) : "memory");
    }
    __syncthreads();

    // ---- Issue the bulk copy: 1024 full rows (32 KB) for this block ----
    if (tid == 0) {
        const char* src = xbytes + (size_t)blockIdx.x * TILE_BYTES;
        asm volatile("mbarrier.arrive.expect_tx.shared.b64 _, [%0], %1;"
                     :: "r"(mbar_a), "r"((uint32_t)TILE_BYTES) : "memory");
        asm volatile(
            "cp.async.bulk.shared::cluster.global.mbarrier::complete_tx::bytes "
            "[%0], [%1], %2, [%3];"
            :: "r"(tile_a), "l"(src), "r"((uint32_t)TILE_BYTES), "r"(mbar_a)
            : "memory");
    }

    // ================= Warp 0: compute T via shuffles (overlaps TMA) =========
    if (tid < 32) {
        // -- 18 half-angle sincos, one per lane (clamped index) --
        float cw, sw;
        {
            const int wi = lane < 18 ? lane : 17;
            __sincosf(0.5f * __ldg(&w[wi]), &sw, &cw);
        }

        // -- Each lane simulates column `lane` of V (lanes >=8 carry junk) --
        float re[8], im[8];
#pragma unroll
        for (int k = 0; k < 8; k++) {
            re[k] = (k == lane) ? 1.0f : 0.0f;
            im[k] = 0.0f;
        }

#pragma unroll
        for (int l = 0; l < 3; l++) {
#pragma unroll
            for (int q = 0; q < 3; q++) {
                const int g = l * 3 + q;
                const float cy = __shfl_sync(FULLMASK, cw, 2 * g);
                const float sy = __shfl_sync(FULLMASK, sw, 2 * g);
                const float cz = __shfl_sync(FULLMASK, cw, 2 * g + 1);
                const float sz = __shfl_sync(FULLMASK, sw, 2 * g + 1);
                const int bit = 4 >> q;  // qubit q occupies bit (2-q)
#pragma unroll
                for (int j = 0; j < 8; j++) {
                    if (j & bit) continue;
                    const int j1 = j | bit;
                    const float r0 = re[j],  i0 = im[j];
                    const float r1 = re[j1], i1 = im[j1];
                    // RY(th)
                    const float nr0 = cy * r0 - sy * r1;
                    const float ni0 = cy * i0 - sy * i1;
                    const float nr1 = sy * r0 + cy * r1;
                    const float ni1 = sy * i0 + cy * i1;
                    // RZ(ph): amp(bit=0) *= cz - i sz ; amp(bit=1) *= cz + i sz
                    re[j]  = cz * nr0 + sz * ni0;
                    im[j]  = cz * ni0 - sz * nr0;
                    re[j1] = cz * nr1 - sz * ni1;
                    im[j1] = cz * ni1 + sz * nr1;
                }
            }
            // CNOT(0,1): control bit4, target bit2
#pragma unroll
            for (int j = 0; j < 8; j++) {
                if ((j & 4) && !(j & 2)) {
                    const int j1 = j | 2;
                    float tmp;
                    tmp = re[j]; re[j] = re[j1]; re[j1] = tmp;
                    tmp = im[j]; im[j] = im[j1]; im[j1] = tmp;
                }
            }
            // CNOT(1,2): control bit2, target bit1
#pragma unroll
            for (int j = 0; j < 8; j++) {
                if ((j & 2) && !(j & 1)) {
                    const int j1 = j | 1;
                    float tmp;
                    tmp = re[j]; re[j] = re[j1]; re[j1] = tmp;
                    tmp = im[j]; im[j] = im[j1]; im[j1] = tmp;
                }
            }
        }

        // -- M = Re(V^H Z0 V): lane holds m0 = M[j0][k0], m1 = M[j0+4][k0] --
        const int j0 = lane >> 3, k0 = lane & 7;
        float m0 = 0.0f, m1 = 0.0f;
#pragma unroll
        for (int r = 0; r < 8; r++) {
            const float arj  = __shfl_sync(FULLMASK, re[r], j0);
            const float aij  = __shfl_sync(FULLMASK, im[r], j0);
            const float arj4 = __shfl_sync(FULLMASK, re[r], j0 + 4);
            const float aij4 = __shfl_sync(FULLMASK, im[r], j0 + 4);
            const float ark  = __shfl_sync(FULLMASK, re[r], k0);
            const float aik  = __shfl_sync(FULLMASK, im[r], k0);
            const float zr = (r < 4) ? 1.0f : -1.0f;
            m0 += zr * (arj  * ark + aij  * aik);
            m1 += zr * (arj4 * ark + aij4 * aik);
        }

        // -- T[a,b,c] (lane < 27): signed 8-term sum of M entries --
        const int a = lane / 9, b = (lane / 3) % 3, c = lane % 3;
        const int fa = (a == 2), fb = (b == 2), fc = (c == 2);
        const int na = (a == 1), nb = (b == 1), nc = (c == 1);
        float acc = 0.0f;
#pragma unroll
        for (int i0 = 0; i0 < 2; i0++)
#pragma unroll
            for (int i1 = 0; i1 < 2; i1++)
#pragma unroll
                for (int i2 = 0; i2 < 2; i2++) {
                    const int j = (i0 << 2) | (i1 << 1) | i2;
                    const int k = ((i0 ^ fa) << 2) | ((i1 ^ fb) << 1) | (i2 ^ fc);
                    const int idx = j * 8 + k;
                    const float v0 = __shfl_sync(FULLMASK, m0, idx & 31);
                    const float v1 = __shfl_sync(FULLMASK, m1, idx & 31);
                    const float mv = i0 ? v1 : v0;  // j>=4 <=> i0
                    const int neg = (na & i0) ^ (nb & i1) ^ (nc & i2);
                    acc += neg ? -mv : mv;
                }

        if (lane < 27) sT[lane] = 0.125f * acc;
        if (lane == 27) sT[27] = 0.0f;
    }

    // ---- Wait for the TMA tile (acquire), then for sT ----
    {
        uint32_t done;
        asm volatile(
            "{\n\t"
            ".reg .pred p;\n\t"
            "mbarrier.try_wait.parity.acquire.cta.shared::cta.b64 p, [%1], %2;\n\t"
            "selp.b32 %0, 1, 0, p;\n\t"
            "}"
            : "=r"(done) : "r"(mbar_a), "r"(0u) : "memory");
        if (!done) {
            asm volatile(
                "{\n\t"
                ".reg .pred P1;\n\t"
                "WAIT_LOOP_%=:\n\t"
                "mbarrier.try_wait.parity.acquire.cta.shared::cta.b64 P1, [%0], %1, 0x989680;\n\t"
                "@P1 bra.uni WAIT_DONE_%=;\n\t"
                "bra.uni WAIT_LOOP_%=;\n\t"
                "WAIT_DONE_%=:\n\t"
                "}"
                :: "r"(mbar_a), "r"(0u) : "memory");
        }
    }
    __syncthreads();

    // ---- T via 7 vector LDS.128 (broadcast) ----
    float T[28];
    {
        const float4* sT4 = (const float4*)sT;
#pragma unroll
        for (int i = 0; i < 7; i++) {
            const float4 t = sT4[i];
            T[4 * i + 0] = t.x; T[4 * i + 1] = t.y;
            T[4 * i + 2] = t.z; T[4 * i + 3] = t.w;
        }
    }

    // ================= Main compute: 4 elements/thread from smem =============
    const int gbase = blockIdx.x * ROWS;
#pragma unroll
    for (int e = 0; e < EPT; e++) {
        const int row = tid + e * TPB;
        const float4 xv = *(const float4*)(tile + 32 * row);  // first 16B of row

        float c0, s0, c1, s1, c2, s2;
        __sincosf(xv.x, &s0, &c0);
        __sincosf(xv.y, &s1, &c1);
        __sincosf(xv.z, &s2, &c2);

        float u[3];
#pragma unroll
        for (int a2 = 0; a2 < 3; a2++) {
            float wb[3];
#pragma unroll
            for (int b2 = 0; b2 < 3; b2++) {
                const float* Tb = &T[a2 * 9 + b2 * 3];
                wb[b2] = Tb[0] + Tb[1] * c2 + Tb[2] * s2;
            }
            u[a2] = wb[0] + wb[1] * c1 + wb[2] * s1;
        }
        out[gbase + row] = u[0] + u[1] * c0 + u[2] * s0;
    }
}

extern "C" void kernel_launch(void* const* d_in, const int* in_sizes, int n_in,
                              void* d_out, int out_size) {
    const char* x = (const char*)d_in[0];          // [BATCH, 8] f32 rows (32B)
    const float* w = (const float*)d_in[1];        // [3, 3, 2]
    float* out = (float*)d_out;                    // [BATCH, 1]

    vqc_kernel<<<NBLOCKS, TPB>>>(x, out, w);
}